// round 14
// baseline (speedup 1.0000x reference)
#include <cuda_runtime.h>
#include <cstdint>

#define B        2
#define N_PRE    50000
#define N_POST   50000
#define N_SYN    10000000
#define N_TYPES  20
#define N_BASIS  5

#define MASK_WORDS (N_PRE / 16)          // 3125 words (2 bits/neuron)
#define N_ROWS     (B * N_POST)          // 100000
#define ACC_GRID   1184                  // 148 SMs x 8 blocks: one resident wave
#define BUILDERS   196                   // blocks that build the mask (196*256 >= 50016)

__device__ uint32_t g_spike_mask[MASK_WORDS];
// Per-(batch,post) x type weight sums. Zero at module load; compact_kernel
// re-zeroes after reading, so it is zero at entry of EVERY kernel_launch call.
__device__ __align__(16) float g_S[N_ROWS * N_TYPES];   // 8 MB, L2-resident
// Mask-ready counter: builders increment once each; reset by compact_kernel.
__device__ unsigned g_done = 0;

// ---------------------------------------------------------------------------
__global__ __launch_bounds__(256)
void accum_kernel(const float* __restrict__ spikes,        // [B, N_PRE]
                  const float* __restrict__ weights,       // [N_SYN]
                  const int4*  __restrict__ syn_idx4,      // [N_SYN/2]
                  const int4*  __restrict__ syn_ids4)      // [N_SYN/4]
{
    __shared__ uint32_t smask[MASK_WORDS];

    const int tid = threadIdx.x;
    const int NG = N_SYN / 4;
    const int stride = gridDim.x * blockDim.x;
    const int g0 = blockIdx.x * blockDim.x + tid;

    // Warm L2 with this thread's first index lines while the mask is built.
    if (g0 < NG) {
        const char* p = (const char*)(syn_idx4 + g0 * 2);
        asm volatile("prefetch.global.L2 [%0];" :: "l"(p));
    }

    // ---- Inline mask build (replaces the prep kernel) ----------------------
    if (blockIdx.x < BUILDERS) {
        int t = blockIdx.x * 256 + tid;
        if (t < ((N_PRE + 31) & ~31)) {
            int n = t;
            bool f0 = false, f1 = false;
            if (n < N_PRE) {
                f0 = (__ldg(spikes + n) != 0.0f);
                f1 = (__ldg(spikes + N_PRE + n) != 0.0f);
            }
            uint32_t b0 = __ballot_sync(0xFFFFFFFFu, f0);
            uint32_t b1 = __ballot_sync(0xFFFFFFFFu, f1);
            int lane = tid & 31;
            if (lane == 0 || lane == 16) {
                uint32_t h0 = (b0 >> lane) & 0xFFFFu;
                uint32_t h1 = (b1 >> lane) & 0xFFFFu;
                uint32_t m = 0;
                #pragma unroll
                for (int j = 0; j < 16; j++)
                    m |= (((h0 >> j) & 1u) | (((h1 >> j) & 1u) << 1)) << (2 * j);
                int w = (n >> 4);
                if (w < MASK_WORDS) g_spike_mask[w] = m;
            }
        }
        __threadfence();               // publish mask words
        __syncthreads();               // all warps of this builder done
        if (tid == 0) atomicAdd(&g_done, 1u);
    }

    // ---- Wait for all builders (one-way flag, thread 0 polls) --------------
    if (tid == 0) {
        while (*(volatile unsigned*)&g_done < BUILDERS) __nanosleep(32);
    }
    __syncthreads();
    __threadfence();                   // order mask reads after the flag

    for (int i = tid; i < MASK_WORDS; i += blockDim.x)
        smask[i] = g_spike_mask[i];
    __syncthreads();

    // ---- Main scatter-accumulate loop (proven R11 body, unchanged) ---------
    const size_t OFF = (size_t)N_POST * N_TYPES;

    for (int g = g0; g < NG; g += stride) {
        int4 u = __ldcs(syn_idx4 + g * 2);     // syn 4g+0:(u.x,u.y) 4g+1:(u.z,u.w)
        int4 v = __ldcs(syn_idx4 + g * 2 + 1); // syn 4g+2:(v.x,v.y) 4g+3:(v.z,v.w)

        uint32_t m0 = (smask[u.y >> 4] >> ((u.y & 15) << 1)) & 3u;
        uint32_t m1 = (smask[u.w >> 4] >> ((u.w & 15) << 1)) & 3u;
        uint32_t m2 = (smask[v.y >> 4] >> ((v.y & 15) << 1)) & 3u;
        uint32_t m3 = (smask[v.w >> 4] >> ((v.w & 15) << 1)) & 3u;

        if ((m0 | m1 | m2 | m3) == 0u) continue;   // ~85% of lanes skip

        float4 wv = __ldg((const float4*)(weights + g * 4));
        int4   tt = __ldg(syn_ids4 + g);

        float* r0 = g_S + (size_t)u.x * N_TYPES + tt.x;
        float* r1 = g_S + (size_t)u.z * N_TYPES + tt.y;
        float* r2 = g_S + (size_t)v.x * N_TYPES + tt.z;
        float* r3 = g_S + (size_t)v.z * N_TYPES + tt.w;

        if (m0 & 1u) atomicAdd(r0,       wv.x);
        if (m0 & 2u) atomicAdd(r0 + OFF, wv.x);
        if (m1 & 1u) atomicAdd(r1,       wv.y);
        if (m1 & 2u) atomicAdd(r1 + OFF, wv.y);
        if (m2 & 1u) atomicAdd(r2,       wv.z);
        if (m2 & 2u) atomicAdd(r2 + OFF, wv.z);
        if (m3 & 1u) atomicAdd(r3,       wv.w);
        if (m3 & 2u) atomicAdd(r3 + OFF, wv.w);
    }
}

// ---------------------------------------------------------------------------
// compact: out[row][r] = sum_t S[row][t] * basis[t][r]; zero S[row]; reset flag.
__global__ __launch_bounds__(256)
void compact_kernel(const float* __restrict__ basis, float* __restrict__ out)
{
    __shared__ float sb[N_TYPES * N_BASIS];
    __shared__ float srow[256 * N_BASIS];

    int tid = threadIdx.x;
    if (tid < N_TYPES * N_BASIS) sb[tid] = basis[tid];
    __syncthreads();

    cudaGridDependencySynchronize();   // wait for accum before touching g_S

    // Reset the mask-ready counter for the next kernel_launch call.
    if (blockIdx.x == 0 && tid == 0) g_done = 0;

    int row = blockIdx.x * 256 + tid;
    if (row < N_ROWS) {
        float4* S4 = (float4*)(g_S + (size_t)row * N_TYPES);
        float4 a = S4[0], b = S4[1], c = S4[2], d = S4[3], e = S4[4];
        float s[N_TYPES] = {a.x,a.y,a.z,a.w, b.x,b.y,b.z,b.w, c.x,c.y,c.z,c.w,
                            d.x,d.y,d.z,d.w, e.x,e.y,e.z,e.w};
        #pragma unroll
        for (int r = 0; r < N_BASIS; r++) {
            float acc = 0.f;
            #pragma unroll
            for (int t = 0; t < N_TYPES; t++)
                acc += s[t] * sb[t * N_BASIS + r];
            srow[tid * N_BASIS + r] = acc;
        }
        float4 z = make_float4(0.f, 0.f, 0.f, 0.f);
        S4[0] = z; S4[1] = z; S4[2] = z; S4[3] = z; S4[4] = z;
    }
    __syncthreads();

    const int total4 = (N_ROWS * N_BASIS) / 4;
    int base4 = blockIdx.x * 320;
    float4* out4 = (float4*)out;
    for (int i = tid; i < 320; i += 256) {
        int o4 = base4 + i;
        if (o4 < total4) {
            const float* p = srow + i * 4;
            out4[o4] = make_float4(p[0], p[1], p[2], p[3]);
        }
    }
}

extern "C" void kernel_launch(void* const* d_in, const int* in_sizes, int n_in,
                              void* d_out, int out_size)
{
    const float* spikes  = (const float*)d_in[0];
    const float* weights = (const float*)d_in[1];
    const float* basis   = (const float*)d_in[2];
    const int4*  syn_idx = (const int4*)d_in[3];
    const int4*  syn_ids = (const int4*)d_in[4];
    float* out = (float*)d_out;

    accum_kernel<<<ACC_GRID, 256>>>(spikes, weights, syn_idx, syn_ids);

    {
        cudaLaunchAttribute attr[1];
        attr[0].id = cudaLaunchAttributeProgrammaticStreamSerialization;
        attr[0].val.programmaticStreamSerializationAllowed = 1;
        cudaLaunchConfig_t cfg = {};
        cfg.gridDim  = dim3((N_ROWS + 255) / 256, 1, 1);
        cfg.blockDim = dim3(256, 1, 1);
        cfg.stream = 0;
        cfg.attrs = attr;
        cfg.numAttrs = 1;
        cudaLaunchKernelEx(&cfg, compact_kernel, basis, out);
    }
}

// round 15
// speedup vs baseline: 1.3355x; 1.3355x over previous
#include <cuda_runtime.h>
#include <cstdint>

#define B        2
#define N_PRE    50000
#define N_POST   50000
#define N_SYN    10000000
#define N_TYPES  20
#define N_BASIS  5

#define MASK_WORDS (N_PRE / 16)          // 3125 words (2 bits/neuron)
#define N_ROWS     (B * N_POST)          // 100000

__device__ uint32_t g_spike_mask[MASK_WORDS];
// Per-(batch,post) x type weight sums. Zero at module load; compact_kernel
// re-zeroes after reading, so it is zero at entry of EVERY kernel_launch call.
__device__ __align__(16) float g_S[N_ROWS * N_TYPES];   // 8 MB

// ---------------------------------------------------------------------------
// prep: ballot-based packed 2-bit spike mask.
__global__ void prep_kernel(const float* __restrict__ spikes)
{
    int tid = blockIdx.x * blockDim.x + threadIdx.x;
    if (tid >= ((N_PRE + 31) & ~31)) return;
    int n = tid;
    bool f0 = false, f1 = false;
    if (n < N_PRE) {
        f0 = (__ldg(spikes + n) != 0.0f);
        f1 = (__ldg(spikes + N_PRE + n) != 0.0f);
    }
    uint32_t b0 = __ballot_sync(0xFFFFFFFFu, f0);
    uint32_t b1 = __ballot_sync(0xFFFFFFFFu, f1);
    int lane = threadIdx.x & 31;
    if (lane == 0 || lane == 16) {
        uint32_t h0 = (b0 >> lane) & 0xFFFFu;
        uint32_t h1 = (b1 >> lane) & 0xFFFFu;
        uint32_t m = 0;
        #pragma unroll
        for (int j = 0; j < 16; j++)
            m |= (((h0 >> j) & 1u) | (((h1 >> j) & 1u) << 1)) << (2 * j);
        int w = (n >> 4);
        if (w < MASK_WORDS) g_spike_mask[w] = m;
    }
}

// ---------------------------------------------------------------------------
__global__ __launch_bounds__(256)
void accum_kernel(const float* __restrict__ weights,       // [N_SYN]
                  const int4*  __restrict__ syn_idx4,      // [N_SYN/2]
                  const int4*  __restrict__ syn_ids4)      // [N_SYN/4]
{
    __shared__ uint32_t smask[MASK_WORDS];

    cudaGridDependencySynchronize();   // wait for prep (PDL)

    for (int i = threadIdx.x; i < MASK_WORDS; i += blockDim.x)
        smask[i] = g_spike_mask[i];
    __syncthreads();

    const int NG = N_SYN / 4;                 // 4 consecutive synapses / thread
    const int stride = gridDim.x * blockDim.x;
    const size_t OFF = (size_t)N_POST * N_TYPES;

    for (int g = blockIdx.x * blockDim.x + threadIdx.x; g < NG; g += stride) {
        int4 u = __ldcs(syn_idx4 + g * 2);     // syn 4g+0:(u.x,u.y) 4g+1:(u.z,u.w)
        int4 v = __ldcs(syn_idx4 + g * 2 + 1); // syn 4g+2:(v.x,v.y) 4g+3:(v.z,v.w)

        uint32_t m0 = (smask[u.y >> 4] >> ((u.y & 15) << 1)) & 3u;
        uint32_t m1 = (smask[u.w >> 4] >> ((u.w & 15) << 1)) & 3u;
        uint32_t m2 = (smask[v.y >> 4] >> ((v.y & 15) << 1)) & 3u;
        uint32_t m3 = (smask[v.w >> 4] >> ((v.w & 15) << 1)) & 3u;

        if ((m0 | m1 | m2 | m3) == 0u) continue;   // ~85% of lanes skip

        float4 wv = __ldg((const float4*)(weights + g * 4));
        int4   tt = __ldg(syn_ids4 + g);

        float* r0 = g_S + (size_t)u.x * N_TYPES + tt.x;
        float* r1 = g_S + (size_t)u.z * N_TYPES + tt.y;
        float* r2 = g_S + (size_t)v.x * N_TYPES + tt.z;
        float* r3 = g_S + (size_t)v.z * N_TYPES + tt.w;

        if (m0 & 1u) atomicAdd(r0,       wv.x);
        if (m0 & 2u) atomicAdd(r0 + OFF, wv.x);
        if (m1 & 1u) atomicAdd(r1,       wv.y);
        if (m1 & 2u) atomicAdd(r1 + OFF, wv.y);
        if (m2 & 1u) atomicAdd(r2,       wv.z);
        if (m2 & 2u) atomicAdd(r2 + OFF, wv.z);
        if (m3 & 1u) atomicAdd(r3,       wv.w);
        if (m3 & 2u) atomicAdd(r3 + OFF, wv.w);
    }
}

// ---------------------------------------------------------------------------
// compact: 8 threads per row. Lane r in [0,5): out[row*5+r] = S[row] . basis[:,r],
// then that lane zeroes S4[r]. Row lives entirely in one warp (8 | 32), and all
// warp loads issue before any store (program order) -> race-free, no barriers.
__global__ __launch_bounds__(256)
void compact_kernel(const float* __restrict__ basis, float* __restrict__ out)
{
    __shared__ float sb[N_TYPES * N_BASIS];

    int tid = threadIdx.x;
    if (tid < N_TYPES * N_BASIS) sb[tid] = basis[tid];
    __syncthreads();

    cudaGridDependencySynchronize();   // wait for accum before touching g_S

    int gid = blockIdx.x * 256 + tid;
    int row = gid >> 3;
    int r   = gid & 7;
    if (row >= N_ROWS || r >= N_BASIS + 0) {
        if (row >= N_ROWS || r >= 5) return;
    }

    float4* S4 = (float4*)(g_S + (size_t)row * N_TYPES);   // 20 floats
    float4 a = S4[0], b = S4[1], c = S4[2], d = S4[3], e = S4[4];
    float s[N_TYPES] = {a.x,a.y,a.z,a.w, b.x,b.y,b.z,b.w, c.x,c.y,c.z,c.w,
                        d.x,d.y,d.z,d.w, e.x,e.y,e.z,e.w};

    float acc = 0.f;
    #pragma unroll
    for (int t = 0; t < N_TYPES; t++)
        acc += s[t] * sb[t * N_BASIS + r];
    out[(size_t)row * N_BASIS + r] = acc;

    // Re-zero this row's r-th float4 (r in [0,5) covers all 5 float4s).
    S4[r] = make_float4(0.f, 0.f, 0.f, 0.f);
}

extern "C" void kernel_launch(void* const* d_in, const int* in_sizes, int n_in,
                              void* d_out, int out_size)
{
    const float* spikes  = (const float*)d_in[0];
    const float* weights = (const float*)d_in[1];
    const float* basis   = (const float*)d_in[2];
    const int4*  syn_idx = (const int4*)d_in[3];
    const int4*  syn_ids = (const int4*)d_in[4];
    float* out = (float*)d_out;

    prep_kernel<<<196, 256>>>(spikes);

    {
        cudaLaunchAttribute attr[1];
        attr[0].id = cudaLaunchAttributeProgrammaticStreamSerialization;
        attr[0].val.programmaticStreamSerializationAllowed = 1;
        cudaLaunchConfig_t cfg = {};
        cfg.gridDim  = dim3(1184, 1, 1);
        cfg.blockDim = dim3(256, 1, 1);
        cfg.stream = 0;
        cfg.attrs = attr;
        cfg.numAttrs = 1;
        cudaLaunchKernelEx(&cfg, accum_kernel, weights, syn_idx, syn_ids);
    }

    {
        cudaLaunchAttribute attr[1];
        attr[0].id = cudaLaunchAttributeProgrammaticStreamSerialization;
        attr[0].val.programmaticStreamSerializationAllowed = 1;
        cudaLaunchConfig_t cfg = {};
        cfg.gridDim  = dim3((N_ROWS * 8 + 255) / 256, 1, 1);   // 3125 blocks
        cfg.blockDim = dim3(256, 1, 1);
        cfg.stream = 0;
        cfg.attrs = attr;
        cfg.numAttrs = 1;
        cudaLaunchKernelEx(&cfg, compact_kernel, basis, out);
    }
}

// round 16
// speedup vs baseline: 1.4322x; 1.0724x over previous
#include <cuda_runtime.h>
#include <cstdint>

#define B        2
#define N_PRE    50000
#define N_POST   50000
#define N_SYN    10000000
#define N_TYPES  20
#define N_BASIS  5

#define MASK_WORDS (N_PRE / 16)          // 3125 words (2 bits/neuron)
#define N_ROWS     (B * N_POST)          // 100000

__device__ uint32_t g_spike_mask[MASK_WORDS];
// COLUMN-MAJOR per-type weight sums: g_S[t * N_ROWS + row], row = b*N_POST+post.
// Zero at module load; compact_kernel re-zeroes after reading, so it is zero
// at entry of EVERY kernel_launch call.
__device__ __align__(16) float g_S[N_TYPES * N_ROWS];   // 8 MB

// ---------------------------------------------------------------------------
// prep: ballot-based packed 2-bit spike mask.
__global__ void prep_kernel(const float* __restrict__ spikes)
{
    int tid = blockIdx.x * blockDim.x + threadIdx.x;
    if (tid >= ((N_PRE + 31) & ~31)) return;
    int n = tid;
    bool f0 = false, f1 = false;
    if (n < N_PRE) {
        f0 = (__ldg(spikes + n) != 0.0f);
        f1 = (__ldg(spikes + N_PRE + n) != 0.0f);
    }
    uint32_t b0 = __ballot_sync(0xFFFFFFFFu, f0);
    uint32_t b1 = __ballot_sync(0xFFFFFFFFu, f1);
    int lane = threadIdx.x & 31;
    if (lane == 0 || lane == 16) {
        uint32_t h0 = (b0 >> lane) & 0xFFFFu;
        uint32_t h1 = (b1 >> lane) & 0xFFFFu;
        uint32_t m = 0;
        #pragma unroll
        for (int j = 0; j < 16; j++)
            m |= (((h0 >> j) & 1u) | (((h1 >> j) & 1u) << 1)) << (2 * j);
        int w = (n >> 4);
        if (w < MASK_WORDS) g_spike_mask[w] = m;
    }
}

// ---------------------------------------------------------------------------
__global__ __launch_bounds__(256)
void accum_kernel(const float* __restrict__ weights,       // [N_SYN]
                  const int4*  __restrict__ syn_idx4,      // [N_SYN/2]
                  const int4*  __restrict__ syn_ids4)      // [N_SYN/4]
{
    __shared__ uint32_t smask[MASK_WORDS];

    const int NG = N_SYN / 4;
    const int stride = gridDim.x * blockDim.x;
    const int g0 = blockIdx.x * blockDim.x + threadIdx.x;

    // Warm L2 with this thread's first index line while prep is running.
    if (g0 < NG) {
        const char* p = (const char*)(syn_idx4 + g0 * 2);
        asm volatile("prefetch.global.L2 [%0];" :: "l"(p));
    }

    cudaGridDependencySynchronize();   // wait for prep (PDL)

    for (int i = threadIdx.x; i < MASK_WORDS; i += blockDim.x)
        smask[i] = g_spike_mask[i];
    __syncthreads();

    for (int g = g0; g < NG; g += stride) {
        int4 u = __ldcs(syn_idx4 + g * 2);     // syn 4g+0:(u.x,u.y) 4g+1:(u.z,u.w)
        int4 v = __ldcs(syn_idx4 + g * 2 + 1); // syn 4g+2:(v.x,v.y) 4g+3:(v.z,v.w)

        uint32_t m0 = (smask[u.y >> 4] >> ((u.y & 15) << 1)) & 3u;
        uint32_t m1 = (smask[u.w >> 4] >> ((u.w & 15) << 1)) & 3u;
        uint32_t m2 = (smask[v.y >> 4] >> ((v.y & 15) << 1)) & 3u;
        uint32_t m3 = (smask[v.w >> 4] >> ((v.w & 15) << 1)) & 3u;

        if ((m0 | m1 | m2 | m3) == 0u) continue;   // ~85% of lanes skip

        float4 wv = __ldg((const float4*)(weights + g * 4));
        int4   tt = __ldg(syn_ids4 + g);

        // Column-major scratch: addr = t * N_ROWS + (b*N_POST + post).
        float* r0 = g_S + (size_t)tt.x * N_ROWS + u.x;
        float* r1 = g_S + (size_t)tt.y * N_ROWS + u.z;
        float* r2 = g_S + (size_t)tt.z * N_ROWS + v.x;
        float* r3 = g_S + (size_t)tt.w * N_ROWS + v.z;

        if (m0 & 1u) atomicAdd(r0,          wv.x);
        if (m0 & 2u) atomicAdd(r0 + N_POST, wv.x);
        if (m1 & 1u) atomicAdd(r1,          wv.y);
        if (m1 & 2u) atomicAdd(r1 + N_POST, wv.y);
        if (m2 & 1u) atomicAdd(r2,          wv.z);
        if (m2 & 2u) atomicAdd(r2 + N_POST, wv.z);
        if (m3 & 1u) atomicAdd(r3,          wv.w);
        if (m3 & 2u) atomicAdd(r3 + N_POST, wv.w);
    }
}

// ---------------------------------------------------------------------------
// compact: one thread per row. 20 independent coalesced loads (column-major),
// 100 FMAs, 5 stores, then 20 coalesced zero-stores (owner thread: race-free).
__global__ __launch_bounds__(256)
void compact_kernel(const float* __restrict__ basis, float* __restrict__ out)
{
    __shared__ float sb[N_TYPES * N_BASIS];

    int tid = threadIdx.x;
    if (tid < N_TYPES * N_BASIS) sb[tid] = basis[tid];
    __syncthreads();

    cudaGridDependencySynchronize();   // wait for accum before touching g_S

    int row = blockIdx.x * 256 + tid;
    if (row >= N_ROWS) return;

    float s[N_TYPES];
    #pragma unroll
    for (int t = 0; t < N_TYPES; t++)
        s[t] = g_S[(size_t)t * N_ROWS + row];   // coalesced, 20-way MLP

    float acc[N_BASIS];
    #pragma unroll
    for (int r = 0; r < N_BASIS; r++) acc[r] = 0.f;
    #pragma unroll
    for (int t = 0; t < N_TYPES; t++) {
        #pragma unroll
        for (int r = 0; r < N_BASIS; r++)
            acc[r] += s[t] * sb[t * N_BASIS + r];
    }

    float* o = out + (size_t)row * N_BASIS;
    o[0] = acc[0]; o[1] = acc[1]; o[2] = acc[2]; o[3] = acc[3]; o[4] = acc[4];

    // Re-zero this row's column entries for the next call (coalesced).
    #pragma unroll
    for (int t = 0; t < N_TYPES; t++)
        g_S[(size_t)t * N_ROWS + row] = 0.f;
}

extern "C" void kernel_launch(void* const* d_in, const int* in_sizes, int n_in,
                              void* d_out, int out_size)
{
    const float* spikes  = (const float*)d_in[0];
    const float* weights = (const float*)d_in[1];
    const float* basis   = (const float*)d_in[2];
    const int4*  syn_idx = (const int4*)d_in[3];
    const int4*  syn_ids = (const int4*)d_in[4];
    float* out = (float*)d_out;

    prep_kernel<<<196, 256>>>(spikes);

    {
        cudaLaunchAttribute attr[1];
        attr[0].id = cudaLaunchAttributeProgrammaticStreamSerialization;
        attr[0].val.programmaticStreamSerializationAllowed = 1;
        cudaLaunchConfig_t cfg = {};
        cfg.gridDim  = dim3(1184, 1, 1);
        cfg.blockDim = dim3(256, 1, 1);
        cfg.stream = 0;
        cfg.attrs = attr;
        cfg.numAttrs = 1;
        cudaLaunchKernelEx(&cfg, accum_kernel, weights, syn_idx, syn_ids);
    }

    {
        cudaLaunchAttribute attr[1];
        attr[0].id = cudaLaunchAttributeProgrammaticStreamSerialization;
        attr[0].val.programmaticStreamSerializationAllowed = 1;
        cudaLaunchConfig_t cfg = {};
        cfg.gridDim  = dim3((N_ROWS + 255) / 256, 1, 1);   // 391 blocks
        cfg.blockDim = dim3(256, 1, 1);
        cfg.stream = 0;
        cfg.attrs = attr;
        cfg.numAttrs = 1;
        cudaLaunchKernelEx(&cfg, compact_kernel, basis, out);
    }
}